// round 16
// baseline (speedup 1.0000x reference)
#include <cuda_runtime.h>
#include <cuda_bf16.h>
#include <math.h>
#include <stdint.h>

#define BATCH 64
#define TT 512
#define LL 4
#define II 4
#define NN 520          // TT+LL+II
#define HH 768
#define NH 4
#define DOUT 192
#define H4 (HH/4)
#define KCH 36          // 36 K-chunks of 64 (hi,hi,lo x 12)

// ---------------- scratch (device globals; no allocations allowed) ----------------
__device__ float g_H[(size_t)BATCH*NN*HH];      // h = X @ W^T
__device__ float g_as[BATCH*NN*NH];             // (h*a_s).sum(-1)
__device__ float g_ad[BATCH*NN*NH];             // (h*a_d).sum(-1)
__device__ int   g_excl[2][BATCH*TT];           // [0]=excluded label idx, [1]=excluded image idx
__device__ __nv_bfloat16 g_Ahi[(size_t)BATCH*NN*HH];  // bf16 hi(X)  (X = hi+lo)
__device__ __nv_bfloat16 g_Alo[(size_t)BATCH*NN*HH];  // bf16 lo(X)
__device__ __nv_bfloat16 g_Wh[(size_t)3*HH*HH];       // bf16 hi(W)
__device__ __nv_bfloat16 g_Wl[(size_t)3*HH*HH];       // bf16 lo(W)

__device__ __forceinline__ float warpSum(float v){
    #pragma unroll
    for (int o=16;o;o>>=1) v += __shfl_xor_sync(0xffffffffu, v, o);
    return v;
}
__device__ __forceinline__ float warpMax(float v){
    #pragma unroll
    for (int o=16;o;o>>=1) v = fmaxf(v, __shfl_xor_sync(0xffffffffu, v, o));
    return v;
}
__device__ __forceinline__ float lrelu(float x){ return x > 0.f ? x : 0.2f*x; }

__device__ __forceinline__ uint32_t smem_u32(const void* p){
    uint32_t a;
    asm("{ .reg .u64 t; cvta.to.shared.u64 t, %1; cvt.u32.u64 %0, t; }" : "=r"(a) : "l"(p));
    return a;
}
__device__ __forceinline__ __nv_bfloat16 bflo(float x, __nv_bfloat16 h){
    return __float2bfloat16(x - __bfloat162float(h));
}

// ---------------- W -> bf16 hi/lo ----------------
__global__ void k_wconv(const float* __restrict__ Ws){
    size_t i = (size_t)blockIdx.x*256 + threadIdx.x;
    if (i >= (size_t)3*HH*HH) return;
    float w = Ws[i];
    __nv_bfloat16 h = __float2bfloat16(w);
    g_Wh[i] = h;
    g_Wl[i] = bflo(w, h);
}

// ---------------- zero alpha accumulators (per layer, before GEMM) ----------------
#define ASZ (BATCH*NN*NH)
__global__ void k_zero(){
    int i = blockIdx.x*256 + threadIdx.x;
    if (i < ASZ) g_as[i] = 0.f;
    else if (i < 2*ASZ) g_ad[i-ASZ] = 0.f;
}

// ---------------- concat [text;label;image] -> hi/lo only ----------------
__global__ void k_concat(const float4* __restrict__ text, const float4* __restrict__ lab,
                         const float4* __restrict__ img)
{
    size_t idx = (size_t)blockIdx.x*blockDim.x + threadIdx.x;
    const size_t total = (size_t)BATCH*NN*H4;
    if (idx >= total) return;
    int b = (int)(idx / (NN*H4));
    int r = (int)(idx % (NN*H4));
    int n = r / H4;
    int k = r % H4;
    float4 v;
    if (n < TT)          v = text[(size_t)b*TT*H4 + (size_t)n*H4 + k];
    else if (n < TT+LL)  v = lab [(size_t)b*LL*H4 + (size_t)(n-TT)*H4 + k];
    else                 v = img [(size_t)b*II*H4 + (size_t)(n-TT-LL)*H4 + k];
    __nv_bfloat16 hx=__float2bfloat16(v.x), hy=__float2bfloat16(v.y);
    __nv_bfloat16 hz=__float2bfloat16(v.z), hw=__float2bfloat16(v.w);
    ((__nv_bfloat162*)g_Ahi)[2*idx]   = __halves2bfloat162(hx,hy);
    ((__nv_bfloat162*)g_Ahi)[2*idx+1] = __halves2bfloat162(hz,hw);
    ((__nv_bfloat162*)g_Alo)[2*idx]   = __halves2bfloat162(bflo(v.x,hx), bflo(v.y,hy));
    ((__nv_bfloat162*)g_Alo)[2*idx+1] = __halves2bfloat162(bflo(v.z,hz), bflo(v.w,hw));
}

// ---------------- dynamic edges ----------------
__global__ void k_excl(const float* __restrict__ text, const float* __restrict__ lab,
                       const float* __restrict__ img)
{
    __shared__ float sh[8*HH];
    __shared__ float sinv[8];
    int b = blockIdx.x;
    int tid = threadIdx.x;
    for (int i=tid;i<LL*HH;i+=blockDim.x) sh[i]       = lab[(size_t)b*LL*HH + i];
    for (int i=tid;i<II*HH;i+=blockDim.x) sh[LL*HH+i] = img[(size_t)b*II*HH + i];
    __syncthreads();
    int wid = tid>>5, lane = tid&31;
    if (wid < 8){
        float s=0.f;
        for (int k=lane;k<HH;k+=32){ float v=sh[wid*HH+k]; s+=v*v; }
        s = warpSum(s);
        if (lane==0) sinv[wid] = 1.f / fmaxf(sqrtf(s), 1e-8f);
    }
    __syncthreads();
    for (int t=wid;t<TT;t+=8){
        const float* xr = text + (size_t)b*TT*HH + (size_t)t*HH;
        float d0=0,d1=0,d2=0,d3=0,d4=0,d5=0,d6=0,d7=0;
        for (int k=lane;k<HH;k+=32){
            float x = xr[k];
            d0+=x*sh[0*HH+k]; d1+=x*sh[1*HH+k]; d2+=x*sh[2*HH+k]; d3+=x*sh[3*HH+k];
            d4+=x*sh[4*HH+k]; d5+=x*sh[5*HH+k]; d6+=x*sh[6*HH+k]; d7+=x*sh[7*HH+k];
        }
        d0=warpSum(d0); d1=warpSum(d1); d2=warpSum(d2); d3=warpSum(d3);
        d4=warpSum(d4); d5=warpSum(d5); d6=warpSum(d6); d7=warpSum(d7);
        if (lane==0){
            float c0=d0*sinv[0], c1=d1*sinv[1], c2=d2*sinv[2], c3=d3*sinv[3];
            int el=0; float bm=c0;
            if (c1<bm){bm=c1;el=1;} if (c2<bm){bm=c2;el=2;} if (c3<bm){bm=c3;el=3;}
            g_excl[0][b*TT+t]=el;
            float e0=d4*sinv[4], e1=d5*sinv[5], e2=d6*sinv[6], e3=d7*sinv[7];
            int ei=0; bm=e0;
            if (e1<bm){bm=e1;ei=1;} if (e2<bm){bm=e2;ei=2;} if (e3<bm){bm=e3;ei=3;}
            g_excl[1][b*TT+t]=ei;
        }
    }
}

// ---------------- mma.sync bf16-split GEMM + fused alpha partials ----------------
// Round-10 config + register-level fragment double buffering (ldmatrix for ks+1
// issued before the MMAs of ks, hiding LDS latency under tensor work).
#define BK 64
#define LDSM 72
#define STG_A (128*LDSM*2)            // 18432
#define STG   (2*STG_A)               // 36864
#define GSMEM (3*STG)                 // 110592 -> 2 CTAs/SM

__device__ __forceinline__ void cp16(uint32_t dst, const void* src){
    asm volatile("cp.async.cg.shared.global [%0], [%1], 16;" :: "r"(dst), "l"(src));
}

__global__ void __launch_bounds__(128,2) k_gemm_mma(int layer,
        const float* __restrict__ aw_s, const float* __restrict__ aw_d)
{
    extern __shared__ __align__(16) char dsm[];
    uint32_t smem = smem_u32(dsm);
    int tid = threadIdx.x, lane = tid&31, wid = tid>>5;
    int warp_m = (wid&1)*64;
    int warp_n = (wid>>1)*64;

    const __nv_bfloat16* Wb  = g_Wh + (size_t)layer*HH*HH;
    const __nv_bfloat16* Wlb = g_Wl + (size_t)layer*HH*HH;
    size_t arow0 = (size_t)blockIdx.x*128;
    size_t brow0 = (size_t)blockIdx.y*128;

    float acc[4][8][4];
    #pragma unroll
    for (int mi=0;mi<4;mi++)
        #pragma unroll
        for (int nj=0;nj<8;nj++)
            #pragma unroll
            for (int r=0;r<4;r++) acc[mi][nj][r]=0.f;

    auto issue = [&](int c, int s){
        const __nv_bfloat16* Asrc = (c<24)? g_Ahi : g_Alo;
        const __nv_bfloat16* Bsrc = (c<12)? Wb : ((c<24)? Wlb : Wb);
        int col = (c%12)*BK;
        uint32_t sa  = smem + s*STG;
        uint32_t sbm = smem + s*STG + STG_A;
        #pragma unroll
        for (int i=0;i<8;i++){
            int idx = tid + i*128;
            int r = idx>>3, q = idx&7;
            cp16(sa + (uint32_t)(r*LDSM + q*8)*2,
                 Asrc + (arow0 + r)*HH + col + q*8);
        }
        #pragma unroll
        for (int i=0;i<8;i++){
            int idx = tid + i*128;
            int r = idx>>3, q = idx&7;
            cp16(sbm + (uint32_t)(r*LDSM + q*8)*2,
                 Bsrc + (brow0 + r)*HH + col + q*8);
        }
        asm volatile("cp.async.commit_group;" ::: "memory");
    };

    issue(0,0);
    issue(1,1);

    uint32_t aF[2][4][4];
    uint32_t bF[2][8][2];

    for (int c=0;c<KCH;c++){
        int s = c%3;
        if (c+1 < KCH) asm volatile("cp.async.wait_group 1;" ::: "memory");
        else           asm volatile("cp.async.wait_group 0;" ::: "memory");
        __syncthreads();
        if (c+2 < KCH) issue(c+2, (c+2)%3);

        uint32_t saA = smem + s*STG;
        uint32_t saB = smem + s*STG + STG_A;

        // ---- load fragments for ks=0 into buffer 0 ----
        {
            int kb = 0;
            #pragma unroll
            for (int mi=0;mi<4;mi++){
                int row = warp_m + mi*16 + (lane&15);
                int col = kb + ((lane>>4)<<3);
                uint32_t ad = saA + (uint32_t)(row*LDSM + col)*2;
                asm volatile("ldmatrix.sync.aligned.m8n8.x4.shared.b16 {%0,%1,%2,%3}, [%4];"
                    : "=r"(aF[0][mi][0]), "=r"(aF[0][mi][1]), "=r"(aF[0][mi][2]), "=r"(aF[0][mi][3])
                    : "r"(ad));
            }
            #pragma unroll
            for (int ng=0;ng<4;ng++){
                int n = warp_n + ng*16 + (lane&7) + ((lane>>4)<<3);
                int k = kb + (((lane>>3)&1)<<3);
                uint32_t ad = saB + (uint32_t)(n*LDSM + k)*2;
                uint32_t r0,r1,r2,r3;
                asm volatile("ldmatrix.sync.aligned.m8n8.x4.shared.b16 {%0,%1,%2,%3}, [%4];"
                    : "=r"(r0), "=r"(r1), "=r"(r2), "=r"(r3) : "r"(ad));
                bF[0][ng*2+0][0]=r0; bF[0][ng*2+0][1]=r1;
                bF[0][ng*2+1][0]=r2; bF[0][ng*2+1][1]=r3;
            }
        }

        #pragma unroll
        for (int ks=0;ks<4;ks++){
            int cb2 = ks&1, nb = (ks&1)^1;
            // prefetch fragments for ks+1 (hidden under the MMAs below)
            if (ks < 3){
                int kb = (ks+1)*16;
                #pragma unroll
                for (int mi=0;mi<4;mi++){
                    int row = warp_m + mi*16 + (lane&15);
                    int col = kb + ((lane>>4)<<3);
                    uint32_t ad = saA + (uint32_t)(row*LDSM + col)*2;
                    asm volatile("ldmatrix.sync.aligned.m8n8.x4.shared.b16 {%0,%1,%2,%3}, [%4];"
                        : "=r"(aF[nb][mi][0]), "=r"(aF[nb][mi][1]), "=r"(aF[nb][mi][2]), "=r"(aF[nb][mi][3])
                        : "r"(ad));
                }
                #pragma unroll
                for (int ng=0;ng<4;ng++){
                    int n = warp_n + ng*16 + (lane&7) + ((lane>>4)<<3);
                    int k = kb + (((lane>>3)&1)<<3);
                    uint32_t ad = saB + (uint32_t)(n*LDSM + k)*2;
                    uint32_t r0,r1,r2,r3;
                    asm volatile("ldmatrix.sync.aligned.m8n8.x4.shared.b16 {%0,%1,%2,%3}, [%4];"
                        : "=r"(r0), "=r"(r1), "=r"(r2), "=r"(r3) : "r"(ad));
                    bF[nb][ng*2+0][0]=r0; bF[nb][ng*2+0][1]=r1;
                    bF[nb][ng*2+1][0]=r2; bF[nb][ng*2+1][1]=r3;
                }
            }
            #pragma unroll
            for (int mi=0;mi<4;mi++)
                #pragma unroll
                for (int nj=0;nj<8;nj++){
                    asm volatile(
                        "mma.sync.aligned.m16n8k16.row.col.f32.bf16.bf16.f32 "
                        "{%0,%1,%2,%3}, {%4,%5,%6,%7}, {%8,%9}, {%0,%1,%2,%3};"
                        : "+f"(acc[mi][nj][0]), "+f"(acc[mi][nj][1]),
                          "+f"(acc[mi][nj][2]), "+f"(acc[mi][nj][3])
                        : "r"(aF[cb2][mi][0]), "r"(aF[cb2][mi][1]), "r"(aF[cb2][mi][2]), "r"(aF[cb2][mi][3]),
                          "r"(bF[cb2][nj][0]), "r"(bF[cb2][nj][1]));
                }
        }
    }

    int g = lane>>2, t2 = (lane&3)*2;
    int cb = (int)brow0 + warp_n;
    int head = cb / DOUT;
    float asv[16], adv2[16];
    #pragma unroll
    for (int nj=0;nj<8;nj++){
        int c = cb + nj*8 + t2;
        asv[nj*2]   = aw_s[c];  asv[nj*2+1]  = aw_s[c+1];
        adv2[nj*2]  = aw_d[c];  adv2[nj*2+1] = aw_d[c+1];
    }
    #pragma unroll
    for (int mi=0;mi<4;mi++){
        size_t row = arow0 + warp_m + mi*16 + g;
        float* cr0 = g_H + row*HH + cb;
        float* cr1 = g_H + (row+8)*HH + cb;
        float s0=0.f,d0=0.f,s1=0.f,d1=0.f;
        #pragma unroll
        for (int nj=0;nj<8;nj++){
            int col = nj*8 + t2;
            *(float2*)(cr0 + col) = make_float2(acc[mi][nj][0], acc[mi][nj][1]);
            *(float2*)(cr1 + col) = make_float2(acc[mi][nj][2], acc[mi][nj][3]);
            s0 += acc[mi][nj][0]*asv[nj*2] + acc[mi][nj][1]*asv[nj*2+1];
            d0 += acc[mi][nj][0]*adv2[nj*2] + acc[mi][nj][1]*adv2[nj*2+1];
            s1 += acc[mi][nj][2]*asv[nj*2] + acc[mi][nj][3]*asv[nj*2+1];
            d1 += acc[mi][nj][2]*adv2[nj*2] + acc[mi][nj][3]*adv2[nj*2+1];
        }
        s0 += __shfl_xor_sync(0xffffffffu, s0, 1); s0 += __shfl_xor_sync(0xffffffffu, s0, 2);
        d0 += __shfl_xor_sync(0xffffffffu, d0, 1); d0 += __shfl_xor_sync(0xffffffffu, d0, 2);
        s1 += __shfl_xor_sync(0xffffffffu, s1, 1); s1 += __shfl_xor_sync(0xffffffffu, s1, 2);
        d1 += __shfl_xor_sync(0xffffffffu, d1, 1); d1 += __shfl_xor_sync(0xffffffffu, d1, 2);
        if ((lane&3)==0){
            atomicAdd(&g_as[row*NH + head], s0);
            atomicAdd(&g_ad[row*NH + head], d0);
            atomicAdd(&g_as[(row+8)*NH + head], s1);
            atomicAdd(&g_ad[(row+8)*NH + head], d1);
        }
    }
}

// ---------------- text dsts: one warp per (b,t); heavy + neighbor text rows in smem ----
#define TXT_SMEM ((10*HH + 8*HH + 32)*4)
__global__ void __launch_bounds__(256) k_text(const float* __restrict__ bias,
        const float* __restrict__ gamma, const float* __restrict__ beta,
        float* __restrict__ outp, int isLast)
{
    extern __shared__ float s_dyn[];
    float* s_tx = s_dyn;               // 10*HH
    float* s_h  = s_dyn + 10*HH;       // 8*HH
    float* s_as = s_dyn + 18*HH;       // 32
    int tid = threadIdx.x;
    int wid = tid>>5, lane = tid & 31;
    int b = blockIdx.x >> 6;
    int t0 = (blockIdx.x & 63)*8;
    size_t nbase = (size_t)b*NN;
    const float* Hb = g_H + nbase*HH;

    {
        const float4* hs = (const float4*)(Hb + (size_t)TT*HH);
        #pragma unroll
        for (int i=0;i<6;i++) ((float4*)s_h)[tid + i*256] = hs[tid + i*256];
        #pragma unroll
        for (int i=0;i<8;i++){
            int idx = tid + i*256;
            if (idx < 1920){
                int lr = idx / 192, q = idx % 192;
                int tg = t0 - 1 + lr;
                float4 v = make_float4(0.f,0.f,0.f,0.f);
                if (tg >= 0 && tg < TT)
                    v = ((const float4*)(Hb + (size_t)tg*HH))[q];
                ((float4*)s_tx)[idx] = v;
            }
        }
        if (tid < 32) s_as[tid] = g_as[(nbase + TT)*NH + tid];
    }
    __syncthreads();

    int t = t0 + wid;
    float* dst; size_t drow;
    if (isLast){ dst = outp; drow = ((size_t)b*TT + t)*HH; }
    else       { dst = 0;    drow = (nbase + t)*HH; }
    size_t xrow = (nbase + t)*HH;

    int el = g_excl[0][b*TT+t], ei = g_excl[1][b*TT+t];
    int srcs[9];
    srcs[0]=t;
    srcs[1]=(t>0)? t-1 : t;
    srcs[2]=(t<TT-1)? t+1 : t;
    srcs[3]=0 + (0>=el);
    srcs[4]=1 + (1>=el);
    srcs[5]=2 + (2>=el);
    srcs[6]=LL + 0 + (0>=ei);
    srcs[7]=LL + 1 + (1>=ei);
    srcs[8]=LL + 2 + (2>=ei);
    bool valid1 = (t>0), valid2 = (t<TT-1);

    float4 adv = ((const float4*)g_ad)[nbase + t];
    float adh[4] = {adv.x, adv.y, adv.z, adv.w};
    float w[9][4];
    float mx[4] = {-1e30f,-1e30f,-1e30f,-1e30f};
    #pragma unroll
    for (int e=0;e<9;e++){
        float4 av;
        if (e < 3) av = ((const float4*)g_as)[nbase + srcs[e]];
        else       av = *(const float4*)&s_as[srcs[e]*4];
        float a[4] = {av.x,av.y,av.z,av.w};
        bool v = (e==1)? valid1 : ((e==2)? valid2 : true);
        #pragma unroll
        for (int h=0;h<4;h++){
            float ev = lrelu(a[h] + adh[h]);
            ev = v ? ev : -1e30f;
            w[e][h]=ev;
            mx[h]=fmaxf(mx[h],ev);
        }
    }
    float den[4]={0,0,0,0};
    #pragma unroll
    for (int e=0;e<9;e++)
        #pragma unroll
        for (int h=0;h<4;h++){ float ex=expf(w[e][h]-mx[h]); w[e][h]=ex; den[h]+=ex; }
    #pragma unroll
    for (int h=0;h<4;h++) den[h] = 1.f/(den[h]+1e-16f);
    #pragma unroll
    for (int e=0;e<9;e++)
        #pragma unroll
        for (int h=0;h<4;h++) w[e][h]*=den[h];

    float acc[24];
    #pragma unroll
    for (int i=0;i<24;i++) acc[i]=0.f;
    #pragma unroll
    for (int e=0;e<3;e++){
        const float* hr = s_tx + (srcs[e] - (t0-1))*HH + lane;
        #pragma unroll
        for (int i=0;i<24;i++) acc[i] += w[e][i/6]*hr[32*i];
    }
    #pragma unroll
    for (int e=3;e<9;e++){
        const float* hr = s_h + srcs[e]*HH + lane;
        #pragma unroll
        for (int i=0;i<24;i++) acc[i] += w[e][i/6]*hr[32*i];
    }
    const __nv_bfloat16* xh = g_Ahi + xrow + lane;
    const __nv_bfloat16* xl = g_Alo + xrow + lane;
    float s=0.f;
    #pragma unroll
    for (int i=0;i<24;i++){
        int c = lane + 32*i;
        float xres = __bfloat162float(xh[32*i]) + __bfloat162float(xl[32*i]);
        float v = fmaxf(acc[i] + bias[c], 0.f) + xres;
        acc[i]=v; s+=v;
    }
    s = warpSum(s);
    float mean = s*(1.f/HH);
    float q=0.f;
    #pragma unroll
    for (int i=0;i<24;i++){ float dd=acc[i]-mean; q+=dd*dd; }
    q = warpSum(q);
    float rstd = rsqrtf(q*(1.f/HH)+1e-5f);
    if (isLast){
        #pragma unroll
        for (int i=0;i<24;i++){
            int c = lane+32*i;
            dst[drow + c] = (acc[i]-mean)*rstd*gamma[c] + beta[c];
        }
    } else {
        #pragma unroll
        for (int i=0;i<24;i++){
            int c = lane+32*i;
            float o = (acc[i]-mean)*rstd*gamma[c] + beta[c];
            __nv_bfloat16 h = __float2bfloat16(o);
            g_Ahi[drow + c] = h;
            g_Alo[drow + c] = bflo(o, h);
        }
    }
}

// ---------------- heavy dsts: TWO blocks per batch, 4 dsts each ----------
#define HV_WSZ (NN*20)
__global__ void __launch_bounds__(768) k_heavy2(const float* __restrict__ bias,
        const float* __restrict__ gamma, const float* __restrict__ beta)
{
    extern __shared__ float s_wt[];          // HV_WSZ floats (41.6KB)
    __shared__ float s_mx[4];
    __shared__ float s_redm[17*4];
    __shared__ float s_redd[17*4];
    __shared__ float s_dinv[16];             // [d*4+h], d local
    __shared__ float s_red[24], s_red2[24];
    __shared__ float s_stats[2];

    int b = blockIdx.x >> 1;
    int half = blockIdx.x & 1;
    int tid = threadIdx.x, wid = tid>>5, lane = tid&31;
    size_t nbase = (size_t)b*NN;
    const int* excl = g_excl[half] + b*TT;

    for (int d=0; d<4; d++){
        float4 adv = ((const float4*)g_ad)[nbase + TT + half*4 + d];
        float e0=-1e30f, e1=-1e30f, e2=-1e30f, e3=-1e30f;
        if (tid < NN){
            bool v = (tid >= TT) || (excl[tid] != d);
            float4 av = ((const float4*)g_as)[nbase + tid];
            if (v){
                e0 = lrelu(av.x + adv.x);
                e1 = lrelu(av.y + adv.y);
                e2 = lrelu(av.z + adv.z);
                e3 = lrelu(av.w + adv.w);
            }
        }
        if (wid < 17){
            float m0=warpMax(e0), m1=warpMax(e1), m2=warpMax(e2), m3=warpMax(e3);
            if (lane==0){ s_redm[wid*4+0]=m0; s_redm[wid*4+1]=m1; s_redm[wid*4+2]=m2; s_redm[wid*4+3]=m3; }
        }
        __syncthreads();
        if (tid < 4){
            float m=-1e30f;
            #pragma unroll
            for (int wg=0; wg<17; wg++) m = fmaxf(m, s_redm[wg*4+tid]);
            s_mx[tid] = m;
        }
        __syncthreads();
        float x0=0.f,x1=0.f,x2=0.f,x3=0.f;
        if (tid < NN){
            x0 = expf(e0 - s_mx[0]);
            x1 = expf(e1 - s_mx[1]);
            x2 = expf(e2 - s_mx[2]);
            x3 = expf(e3 - s_mx[3]);
            s_wt[tid*20 + 0*4 + d] = x0;
            s_wt[tid*20 + 1*4 + d] = x1;
            s_wt[tid*20 + 2*4 + d] = x2;
            s_wt[tid*20 + 3*4 + d] = x3;
        }
        if (wid < 17){
            float d0=warpSum(x0), d1=warpSum(x1), d2=warpSum(x2), d3=warpSum(x3);
            if (lane==0){ s_redd[wid*4+0]=d0; s_redd[wid*4+1]=d1; s_redd[wid*4+2]=d2; s_redd[wid*4+3]=d3; }
        }
        __syncthreads();
        if (tid < 4){
            float sm=0.f;
            #pragma unroll
            for (int wg=0; wg<17; wg++) sm += s_redd[wg*4+tid];
            s_dinv[d*4+tid] = 1.f/(sm + 1e-16f);
        }
        __syncthreads();
    }

    int c = tid;
    int h = c / DOUT;
    const float* Hb = g_H + nbase*HH;
    float a[4];
    #pragma unroll
    for (int d=0;d<4;d++) a[d]=0.f;
    for (int t=0; t<NN; t++){
        float hr = Hb[(size_t)t*HH + c];
        float4 w0 = *(const float4*)&s_wt[t*20 + h*4];
        a[0] += w0.x*hr; a[1] += w0.y*hr; a[2] += w0.z*hr; a[3] += w0.w*hr;
    }
    float y[4];
    float bi = bias[c];
    #pragma unroll
    for (int d=0;d<4;d++){
        size_t row = (nbase + TT + half*4 + d)*HH;
        float xres = __bfloat162float(g_Ahi[row + c]) + __bfloat162float(g_Alo[row + c]);
        float agg = a[d]*s_dinv[d*4+h];
        y[d] = fmaxf(agg + bi, 0.f) + xres;
    }

    float gm = gamma[c], bt = beta[c];
    for (int d=0;d<4;d++){
        float ps = warpSum(y[d]);
        float pq = warpSum(y[d]*y[d]);
        if (lane==0){ s_red[wid]=ps; s_red2[wid]=pq; }
        __syncthreads();
        if (tid==0){
            float S=0.f,Q=0.f;
            #pragma unroll
            for (int wg=0;wg<24;wg++){ S+=s_red[wg]; Q+=s_red2[wg]; }
            float mean = S*(1.f/HH);
            float var  = Q*(1.f/HH) - mean*mean;
            s_stats[0]=mean;
            s_stats[1]=rsqrtf(fmaxf(var,0.f)+1e-5f);
        }
        __syncthreads();
        float mean=s_stats[0], rstd=s_stats[1];
        size_t row = (nbase + TT + half*4 + d)*HH;
        float o = (y[d]-mean)*rstd*gm + bt;
        __nv_bfloat16 hh = __float2bfloat16(o);
        g_Ahi[row + c] = hh;
        g_Alo[row + c] = bflo(o, hh);
        __syncthreads();
    }
}

// ---------------- launch ----------------
extern "C" void kernel_launch(void* const* d_in, const int* in_sizes, int n_in,
                              void* d_out, int out_size)
{
    const float* text = (const float*)d_in[0];
    const float* lab  = (const float*)d_in[1];
    const float* img  = (const float*)d_in[2];
    const float* Ws   = (const float*)d_in[3];
    const float* aws  = (const float*)d_in[4];
    const float* awd  = (const float*)d_in[5];
    const float* bias = (const float*)d_in[6];
    const float* gam  = (const float*)d_in[7];
    const float* bet  = (const float*)d_in[8];
    float* outp = (float*)d_out;

    cudaFuncSetAttribute(k_gemm_mma, cudaFuncAttributeMaxDynamicSharedMemorySize, GSMEM);
    cudaFuncSetAttribute(k_heavy2, cudaFuncAttributeMaxDynamicSharedMemorySize, HV_WSZ*4);
    cudaFuncSetAttribute(k_text, cudaFuncAttributeMaxDynamicSharedMemorySize, TXT_SMEM);

    k_wconv<<<(3*HH*HH + 255)/256, 256>>>(Ws);
    {
        size_t total = (size_t)BATCH*NN*H4;
        int blocks = (int)((total + 255)/256);
        k_concat<<<blocks,256>>>((const float4*)text,(const float4*)lab,(const float4*)img);
    }
    k_excl<<<BATCH,256>>>(text, lab, img);

    for (int l=0;l<3;l++){
        k_zero<<<(2*ASZ + 255)/256, 256>>>();
        k_gemm_mma<<<dim3((BATCH*NN)/128, HH/128), 128, GSMEM>>>(l, aws + l*HH, awd + l*HH);
        int last = (l==2);
        k_text<<<(BATCH*TT)/8, 256, TXT_SMEM>>>(bias+l*HH, gam+l*HH, bet+l*HH, outp, last);
        if (!last) k_heavy2<<<BATCH*2, 768, HV_WSZ*4>>>(bias+l*HH, gam+l*HH, bet+l*HH);
    }
}

// round 17
// speedup vs baseline: 1.0184x; 1.0184x over previous
#include <cuda_runtime.h>
#include <cuda_bf16.h>
#include <math.h>
#include <stdint.h>

#define BATCH 64
#define TT 512
#define LL 4
#define II 4
#define NN 520          // TT+LL+II
#define HH 768
#define NH 4
#define DOUT 192
#define H4 (HH/4)
#define KCH 36          // 36 K-chunks of 64 (hi,hi,lo x 12)
#define NTILE_M ((BATCH*NN)/128)   // 260
#define NTILE_N (HH/128)           // 6
#define NTILES (NTILE_M*NTILE_N)   // 1560

// ---------------- scratch (device globals; no allocations allowed) ----------------
__device__ float g_H[(size_t)BATCH*NN*HH];      // h = X @ W^T
__device__ float g_as[BATCH*NN*NH];             // (h*a_s).sum(-1)
__device__ float g_ad[BATCH*NN*NH];             // (h*a_d).sum(-1)
__device__ int   g_excl[2][BATCH*TT];           // [0]=excluded label idx, [1]=excluded image idx
__device__ unsigned int g_tile;                 // work-stealing tile counter
__device__ __nv_bfloat16 g_Ahi[(size_t)BATCH*NN*HH];  // bf16 hi(X)  (X = hi+lo)
__device__ __nv_bfloat16 g_Alo[(size_t)BATCH*NN*HH];  // bf16 lo(X)
__device__ __nv_bfloat16 g_Wh[(size_t)3*HH*HH];       // bf16 hi(W)
__device__ __nv_bfloat16 g_Wl[(size_t)3*HH*HH];       // bf16 lo(W)

__device__ __forceinline__ float warpSum(float v){
    #pragma unroll
    for (int o=16;o;o>>=1) v += __shfl_xor_sync(0xffffffffu, v, o);
    return v;
}
__device__ __forceinline__ float warpMax(float v){
    #pragma unroll
    for (int o=16;o;o>>=1) v = fmaxf(v, __shfl_xor_sync(0xffffffffu, v, o));
    return v;
}
__device__ __forceinline__ float lrelu(float x){ return x > 0.f ? x : 0.2f*x; }

__device__ __forceinline__ uint32_t smem_u32(const void* p){
    uint32_t a;
    asm("{ .reg .u64 t; cvta.to.shared.u64 t, %1; cvt.u32.u64 %0, t; }" : "=r"(a) : "l"(p));
    return a;
}
__device__ __forceinline__ __nv_bfloat16 bflo(float x, __nv_bfloat16 h){
    return __float2bfloat16(x - __bfloat162float(h));
}

// ---------------- W -> bf16 hi/lo ----------------
__global__ void k_wconv(const float* __restrict__ Ws){
    size_t i = (size_t)blockIdx.x*256 + threadIdx.x;
    if (i >= (size_t)3*HH*HH) return;
    float w = Ws[i];
    __nv_bfloat16 h = __float2bfloat16(w);
    g_Wh[i] = h;
    g_Wl[i] = bflo(w, h);
}

// ---------------- zero alpha accumulators + tile counter (per layer) ----------------
#define ASZ (BATCH*NN*NH)
__global__ void k_zero(){
    int i = blockIdx.x*256 + threadIdx.x;
    if (i == 0) g_tile = 0u;
    if (i < ASZ) g_as[i] = 0.f;
    else if (i < 2*ASZ) g_ad[i-ASZ] = 0.f;
}

// ---------------- concat [text;label;image] -> hi/lo only ----------------
__global__ void k_concat(const float4* __restrict__ text, const float4* __restrict__ lab,
                         const float4* __restrict__ img)
{
    size_t idx = (size_t)blockIdx.x*blockDim.x + threadIdx.x;
    const size_t total = (size_t)BATCH*NN*H4;
    if (idx >= total) return;
    int b = (int)(idx / (NN*H4));
    int r = (int)(idx % (NN*H4));
    int n = r / H4;
    int k = r % H4;
    float4 v;
    if (n < TT)          v = text[(size_t)b*TT*H4 + (size_t)n*H4 + k];
    else if (n < TT+LL)  v = lab [(size_t)b*LL*H4 + (size_t)(n-TT)*H4 + k];
    else                 v = img [(size_t)b*II*H4 + (size_t)(n-TT-LL)*H4 + k];
    __nv_bfloat16 hx=__float2bfloat16(v.x), hy=__float2bfloat16(v.y);
    __nv_bfloat16 hz=__float2bfloat16(v.z), hw=__float2bfloat16(v.w);
    ((__nv_bfloat162*)g_Ahi)[2*idx]   = __halves2bfloat162(hx,hy);
    ((__nv_bfloat162*)g_Ahi)[2*idx+1] = __halves2bfloat162(hz,hw);
    ((__nv_bfloat162*)g_Alo)[2*idx]   = __halves2bfloat162(bflo(v.x,hx), bflo(v.y,hy));
    ((__nv_bfloat162*)g_Alo)[2*idx+1] = __halves2bfloat162(bflo(v.z,hz), bflo(v.w,hw));
}

// ---------------- dynamic edges ----------------
__global__ void k_excl(const float* __restrict__ text, const float* __restrict__ lab,
                       const float* __restrict__ img)
{
    __shared__ float sh[8*HH];
    __shared__ float sinv[8];
    int b = blockIdx.x;
    int tid = threadIdx.x;
    for (int i=tid;i<LL*HH;i+=blockDim.x) sh[i]       = lab[(size_t)b*LL*HH + i];
    for (int i=tid;i<II*HH;i+=blockDim.x) sh[LL*HH+i] = img[(size_t)b*II*HH + i];
    __syncthreads();
    int wid = tid>>5, lane = tid&31;
    if (wid < 8){
        float s=0.f;
        for (int k=lane;k<HH;k+=32){ float v=sh[wid*HH+k]; s+=v*v; }
        s = warpSum(s);
        if (lane==0) sinv[wid] = 1.f / fmaxf(sqrtf(s), 1e-8f);
    }
    __syncthreads();
    for (int t=wid;t<TT;t+=8){
        const float* xr = text + (size_t)b*TT*HH + (size_t)t*HH;
        float d0=0,d1=0,d2=0,d3=0,d4=0,d5=0,d6=0,d7=0;
        for (int k=lane;k<HH;k+=32){
            float x = xr[k];
            d0+=x*sh[0*HH+k]; d1+=x*sh[1*HH+k]; d2+=x*sh[2*HH+k]; d3+=x*sh[3*HH+k];
            d4+=x*sh[4*HH+k]; d5+=x*sh[5*HH+k]; d6+=x*sh[6*HH+k]; d7+=x*sh[7*HH+k];
        }
        d0=warpSum(d0); d1=warpSum(d1); d2=warpSum(d2); d3=warpSum(d3);
        d4=warpSum(d4); d5=warpSum(d5); d6=warpSum(d6); d7=warpSum(d7);
        if (lane==0){
            float c0=d0*sinv[0], c1=d1*sinv[1], c2=d2*sinv[2], c3=d3*sinv[3];
            int el=0; float bm=c0;
            if (c1<bm){bm=c1;el=1;} if (c2<bm){bm=c2;el=2;} if (c3<bm){bm=c3;el=3;}
            g_excl[0][b*TT+t]=el;
            float e0=d4*sinv[4], e1=d5*sinv[5], e2=d6*sinv[6], e3=d7*sinv[7];
            int ei=0; bm=e0;
            if (e1<bm){bm=e1;ei=1;} if (e2<bm){bm=e2;ei=2;} if (e3<bm){bm=e3;ei=3;}
            g_excl[1][b*TT+t]=ei;
        }
    }
}

// ---------------- persistent work-stealing bf16-split GEMM + fused alpha ----------------
// R10-validated 128x128 tile / 4-warp / 3-stage pipeline body; CTAs loop over tiles
// fetched from a global atomic counter (kills the 6-wave quantization tail).
#define BK 64
#define LDSM 72
#define STG_A (128*LDSM*2)            // 18432
#define STG   (2*STG_A)               // 36864
#define GSMEM (3*STG)                 // 110592 -> 2 CTAs/SM

__device__ __forceinline__ void cp16(uint32_t dst, const void* src){
    asm volatile("cp.async.cg.shared.global [%0], [%1], 16;" :: "r"(dst), "l"(src));
}

__global__ void __launch_bounds__(128,2) k_gemm_mma(int layer,
        const float* __restrict__ aw_s, const float* __restrict__ aw_d)
{
    extern __shared__ __align__(16) char dsm[];
    __shared__ unsigned int s_tile;
    uint32_t smem = smem_u32(dsm);
    int tid = threadIdx.x, lane = tid&31, wid = tid>>5;
    int warp_m = (wid&1)*64;
    int warp_n = (wid>>1)*64;

    const __nv_bfloat16* Wb  = g_Wh + (size_t)layer*HH*HH;
    const __nv_bfloat16* Wlb = g_Wl + (size_t)layer*HH*HH;

    for (;;){
        if (tid == 0) s_tile = atomicAdd(&g_tile, 1u);
        __syncthreads();
        unsigned int tile = s_tile;
        if (tile >= NTILES) break;
        size_t arow0 = (size_t)(tile / NTILE_N)*128;   // M-tile (slow -> A L2 reuse)
        size_t brow0 = (size_t)(tile % NTILE_N)*128;   // N-tile

        float acc[4][8][4];
        #pragma unroll
        for (int mi=0;mi<4;mi++)
            #pragma unroll
            for (int nj=0;nj<8;nj++)
                #pragma unroll
                for (int r=0;r<4;r++) acc[mi][nj][r]=0.f;

        auto issue = [&](int c, int s){
            const __nv_bfloat16* Asrc = (c<24)? g_Ahi : g_Alo;
            const __nv_bfloat16* Bsrc = (c<12)? Wb : ((c<24)? Wlb : Wb);
            int col = (c%12)*BK;
            uint32_t sa  = smem + s*STG;
            uint32_t sbm = smem + s*STG + STG_A;
            #pragma unroll
            for (int i=0;i<8;i++){
                int idx = tid + i*128;
                int r = idx>>3, q = idx&7;
                cp16(sa + (uint32_t)(r*LDSM + q*8)*2,
                     Asrc + (arow0 + r)*HH + col + q*8);
            }
            #pragma unroll
            for (int i=0;i<8;i++){
                int idx = tid + i*128;
                int r = idx>>3, q = idx&7;
                cp16(sbm + (uint32_t)(r*LDSM + q*8)*2,
                     Bsrc + (brow0 + r)*HH + col + q*8);
            }
            asm volatile("cp.async.commit_group;" ::: "memory");
        };

        issue(0,0);
        issue(1,1);

        for (int c=0;c<KCH;c++){
            int s = c%3;
            if (c+1 < KCH) asm volatile("cp.async.wait_group 1;" ::: "memory");
            else           asm volatile("cp.async.wait_group 0;" ::: "memory");
            __syncthreads();
            if (c+2 < KCH) issue(c+2, (c+2)%3);

            uint32_t saA = smem + s*STG;
            uint32_t saB = smem + s*STG + STG_A;
            #pragma unroll
            for (int ks=0;ks<4;ks++){
                int kb = ks*16;
                uint32_t aF[4][4];
                uint32_t bF[8][2];
                #pragma unroll
                for (int mi=0;mi<4;mi++){
                    int row = warp_m + mi*16 + (lane&15);
                    int col = kb + ((lane>>4)<<3);
                    uint32_t ad = saA + (uint32_t)(row*LDSM + col)*2;
                    asm volatile("ldmatrix.sync.aligned.m8n8.x4.shared.b16 {%0,%1,%2,%3}, [%4];"
                        : "=r"(aF[mi][0]), "=r"(aF[mi][1]), "=r"(aF[mi][2]), "=r"(aF[mi][3])
                        : "r"(ad));
                }
                #pragma unroll
                for (int ng=0;ng<4;ng++){
                    int n = warp_n + ng*16 + (lane&7) + ((lane>>4)<<3);
                    int k = kb + (((lane>>3)&1)<<3);
                    uint32_t ad = saB + (uint32_t)(n*LDSM + k)*2;
                    uint32_t r0,r1,r2,r3;
                    asm volatile("ldmatrix.sync.aligned.m8n8.x4.shared.b16 {%0,%1,%2,%3}, [%4];"
                        : "=r"(r0), "=r"(r1), "=r"(r2), "=r"(r3) : "r"(ad));
                    bF[ng*2+0][0]=r0; bF[ng*2+0][1]=r1;
                    bF[ng*2+1][0]=r2; bF[ng*2+1][1]=r3;
                }
                #pragma unroll
                for (int mi=0;mi<4;mi++)
                    #pragma unroll
                    for (int nj=0;nj<8;nj++){
                        asm volatile(
                            "mma.sync.aligned.m16n8k16.row.col.f32.bf16.bf16.f32 "
                            "{%0,%1,%2,%3}, {%4,%5,%6,%7}, {%8,%9}, {%0,%1,%2,%3};"
                            : "+f"(acc[mi][nj][0]), "+f"(acc[mi][nj][1]),
                              "+f"(acc[mi][nj][2]), "+f"(acc[mi][nj][3])
                            : "r"(aF[mi][0]), "r"(aF[mi][1]), "r"(aF[mi][2]), "r"(aF[mi][3]),
                              "r"(bF[nj][0]), "r"(bF[nj][1]));
                    }
            }
        }

        // epilogue: write H + fused alpha partials (64-col warp block within one head)
        int g = lane>>2, t2 = (lane&3)*2;
        int cb = (int)brow0 + warp_n;
        int head = cb / DOUT;
        float asv[16], adv2[16];
        #pragma unroll
        for (int nj=0;nj<8;nj++){
            int c = cb + nj*8 + t2;
            asv[nj*2]   = aw_s[c];  asv[nj*2+1]  = aw_s[c+1];
            adv2[nj*2]  = aw_d[c];  adv2[nj*2+1] = aw_d[c+1];
        }
        #pragma unroll
        for (int mi=0;mi<4;mi++){
            size_t row = arow0 + warp_m + mi*16 + g;
            float* cr0 = g_H + row*HH + cb;
            float* cr1 = g_H + (row+8)*HH + cb;
            float s0=0.f,d0=0.f,s1=0.f,d1=0.f;
            #pragma unroll
            for (int nj=0;nj<8;nj++){
                int col = nj*8 + t2;
                *(float2*)(cr0 + col) = make_float2(acc[mi][nj][0], acc[mi][nj][1]);
                *(float2*)(cr1 + col) = make_float2(acc[mi][nj][2], acc[mi][nj][3]);
                s0 += acc[mi][nj][0]*asv[nj*2] + acc[mi][nj][1]*asv[nj*2+1];
                d0 += acc[mi][nj][0]*adv2[nj*2] + acc[mi][nj][1]*adv2[nj*2+1];
                s1 += acc[mi][nj][2]*asv[nj*2] + acc[mi][nj][3]*asv[nj*2+1];
                d1 += acc[mi][nj][2]*adv2[nj*2] + acc[mi][nj][3]*adv2[nj*2+1];
            }
            s0 += __shfl_xor_sync(0xffffffffu, s0, 1); s0 += __shfl_xor_sync(0xffffffffu, s0, 2);
            d0 += __shfl_xor_sync(0xffffffffu, d0, 1); d0 += __shfl_xor_sync(0xffffffffu, d0, 2);
            s1 += __shfl_xor_sync(0xffffffffu, s1, 1); s1 += __shfl_xor_sync(0xffffffffu, s1, 2);
            d1 += __shfl_xor_sync(0xffffffffu, d1, 1); d1 += __shfl_xor_sync(0xffffffffu, d1, 2);
            if ((lane&3)==0){
                atomicAdd(&g_as[row*NH + head], s0);
                atomicAdd(&g_ad[row*NH + head], d0);
                atomicAdd(&g_as[(row+8)*NH + head], s1);
                atomicAdd(&g_ad[(row+8)*NH + head], d1);
            }
        }
    }
}

// ---------------- text dsts: one warp per (b,t); heavy + neighbor text rows in smem ----
#define TXT_SMEM ((10*HH + 8*HH + 32)*4)
__global__ void __launch_bounds__(256) k_text(const float* __restrict__ bias,
        const float* __restrict__ gamma, const float* __restrict__ beta,
        float* __restrict__ outp, int isLast)
{
    extern __shared__ float s_dyn[];
    float* s_tx = s_dyn;               // 10*HH
    float* s_h  = s_dyn + 10*HH;       // 8*HH
    float* s_as = s_dyn + 18*HH;       // 32
    int tid = threadIdx.x;
    int wid = tid>>5, lane = tid & 31;
    int b = blockIdx.x >> 6;
    int t0 = (blockIdx.x & 63)*8;
    size_t nbase = (size_t)b*NN;
    const float* Hb = g_H + nbase*HH;

    {
        const float4* hs = (const float4*)(Hb + (size_t)TT*HH);
        #pragma unroll
        for (int i=0;i<6;i++) ((float4*)s_h)[tid + i*256] = hs[tid + i*256];
        #pragma unroll
        for (int i=0;i<8;i++){
            int idx = tid + i*256;
            if (idx < 1920){
                int lr = idx / 192, q = idx % 192;
                int tg = t0 - 1 + lr;
                float4 v = make_float4(0.f,0.f,0.f,0.f);
                if (tg >= 0 && tg < TT)
                    v = ((const float4*)(Hb + (size_t)tg*HH))[q];
                ((float4*)s_tx)[idx] = v;
            }
        }
        if (tid < 32) s_as[tid] = g_as[(nbase + TT)*NH + tid];
    }
    __syncthreads();

    int t = t0 + wid;
    float* dst; size_t drow;
    if (isLast){ dst = outp; drow = ((size_t)b*TT + t)*HH; }
    else       { dst = 0;    drow = (nbase + t)*HH; }
    size_t xrow = (nbase + t)*HH;

    int el = g_excl[0][b*TT+t], ei = g_excl[1][b*TT+t];
    int srcs[9];
    srcs[0]=t;
    srcs[1]=(t>0)? t-1 : t;
    srcs[2]=(t<TT-1)? t+1 : t;
    srcs[3]=0 + (0>=el);
    srcs[4]=1 + (1>=el);
    srcs[5]=2 + (2>=el);
    srcs[6]=LL + 0 + (0>=ei);
    srcs[7]=LL + 1 + (1>=ei);
    srcs[8]=LL + 2 + (2>=ei);
    bool valid1 = (t>0), valid2 = (t<TT-1);

    float4 adv = ((const float4*)g_ad)[nbase + t];
    float adh[4] = {adv.x, adv.y, adv.z, adv.w};
    float w[9][4];
    float mx[4] = {-1e30f,-1e30f,-1e30f,-1e30f};
    #pragma unroll
    for (int e=0;e<9;e++){
        float4 av;
        if (e < 3) av = ((const float4*)g_as)[nbase + srcs[e]];
        else       av = *(const float4*)&s_as[srcs[e]*4];
        float a[4] = {av.x,av.y,av.z,av.w};
        bool v = (e==1)? valid1 : ((e==2)? valid2 : true);
        #pragma unroll
        for (int h=0;h<4;h++){
            float ev = lrelu(a[h] + adh[h]);
            ev = v ? ev : -1e30f;
            w[e][h]=ev;
            mx[h]=fmaxf(mx[h],ev);
        }
    }
    float den[4]={0,0,0,0};
    #pragma unroll
    for (int e=0;e<9;e++)
        #pragma unroll
        for (int h=0;h<4;h++){ float ex=expf(w[e][h]-mx[h]); w[e][h]=ex; den[h]+=ex; }
    #pragma unroll
    for (int h=0;h<4;h++) den[h] = 1.f/(den[h]+1e-16f);
    #pragma unroll
    for (int e=0;e<9;e++)
        #pragma unroll
        for (int h=0;h<4;h++) w[e][h]*=den[h];

    float acc[24];
    #pragma unroll
    for (int i=0;i<24;i++) acc[i]=0.f;
    #pragma unroll
    for (int e=0;e<3;e++){
        const float* hr = s_tx + (srcs[e] - (t0-1))*HH + lane;
        #pragma unroll
        for (int i=0;i<24;i++) acc[i] += w[e][i/6]*hr[32*i];
    }
    #pragma unroll
    for (int e=3;e<9;e++){
        const float* hr = s_h + srcs[e]*HH + lane;
        #pragma unroll
        for (int i=0;i<24;i++) acc[i] += w[e][i/6]*hr[32*i];
    }
    const __nv_bfloat16* xh = g_Ahi + xrow + lane;
    const __nv_bfloat16* xl = g_Alo + xrow + lane;
    float s=0.f;
    #pragma unroll
    for (int i=0;i<24;i++){
        int c = lane + 32*i;
        float xres = __bfloat162float(xh[32*i]) + __bfloat162float(xl[32*i]);
        float v = fmaxf(acc[i] + bias[c], 0.f) + xres;
        acc[i]=v; s+=v;
    }
    s = warpSum(s);
    float mean = s*(1.f/HH);
    float q=0.f;
    #pragma unroll
    for (int i=0;i<24;i++){ float dd=acc[i]-mean; q+=dd*dd; }
    q = warpSum(q);
    float rstd = rsqrtf(q*(1.f/HH)+1e-5f);
    if (isLast){
        #pragma unroll
        for (int i=0;i<24;i++){
            int c = lane+32*i;
            dst[drow + c] = (acc[i]-mean)*rstd*gamma[c] + beta[c];
        }
    } else {
        #pragma unroll
        for (int i=0;i<24;i++){
            int c = lane+32*i;
            float o = (acc[i]-mean)*rstd*gamma[c] + beta[c];
            __nv_bfloat16 h = __float2bfloat16(o);
            g_Ahi[drow + c] = h;
            g_Alo[drow + c] = bflo(o, h);
        }
    }
}

// ---------------- heavy dsts: TWO blocks per batch, 4 dsts each ----------
#define HV_WSZ (NN*20)
__global__ void __launch_bounds__(768) k_heavy2(const float* __restrict__ bias,
        const float* __restrict__ gamma, const float* __restrict__ beta)
{
    extern __shared__ float s_wt[];          // HV_WSZ floats (41.6KB)
    __shared__ float s_mx[4];
    __shared__ float s_redm[17*4];
    __shared__ float s_redd[17*4];
    __shared__ float s_dinv[16];             // [d*4+h], d local
    __shared__ float s_red[24], s_red2[24];
    __shared__ float s_stats[2];

    int b = blockIdx.x >> 1;
    int half = blockIdx.x & 1;
    int tid = threadIdx.x, wid = tid>>5, lane = tid&31;
    size_t nbase = (size_t)b*NN;
    const int* excl = g_excl[half] + b*TT;

    for (int d=0; d<4; d++){
        float4 adv = ((const float4*)g_ad)[nbase + TT + half*4 + d];
        float e0=-1e30f, e1=-1e30f, e2=-1e30f, e3=-1e30f;
        if (tid < NN){
            bool v = (tid >= TT) || (excl[tid] != d);
            float4 av = ((const float4*)g_as)[nbase + tid];
            if (v){
                e0 = lrelu(av.x + adv.x);
                e1 = lrelu(av.y + adv.y);
                e2 = lrelu(av.z + adv.z);
                e3 = lrelu(av.w + adv.w);
            }
        }
        if (wid < 17){
            float m0=warpMax(e0), m1=warpMax(e1), m2=warpMax(e2), m3=warpMax(e3);
            if (lane==0){ s_redm[wid*4+0]=m0; s_redm[wid*4+1]=m1; s_redm[wid*4+2]=m2; s_redm[wid*4+3]=m3; }
        }
        __syncthreads();
        if (tid < 4){
            float m=-1e30f;
            #pragma unroll
            for (int wg=0; wg<17; wg++) m = fmaxf(m, s_redm[wg*4+tid]);
            s_mx[tid] = m;
        }
        __syncthreads();
        float x0=0.f,x1=0.f,x2=0.f,x3=0.f;
        if (tid < NN){
            x0 = expf(e0 - s_mx[0]);
            x1 = expf(e1 - s_mx[1]);
            x2 = expf(e2 - s_mx[2]);
            x3 = expf(e3 - s_mx[3]);
            s_wt[tid*20 + 0*4 + d] = x0;
            s_wt[tid*20 + 1*4 + d] = x1;
            s_wt[tid*20 + 2*4 + d] = x2;
            s_wt[tid*20 + 3*4 + d] = x3;
        }
        if (wid < 17){
            float d0=warpSum(x0), d1=warpSum(x1), d2=warpSum(x2), d3=warpSum(x3);
            if (lane==0){ s_redd[wid*4+0]=d0; s_redd[wid*4+1]=d1; s_redd[wid*4+2]=d2; s_redd[wid*4+3]=d3; }
        }
        __syncthreads();
        if (tid < 4){
            float sm=0.f;
            #pragma unroll
            for (int wg=0; wg<17; wg++) sm += s_redd[wg*4+tid];
            s_dinv[d*4+tid] = 1.f/(sm + 1e-16f);
        }
        __syncthreads();
    }

    int c = tid;
    int h = c / DOUT;
    const float* Hb = g_H + nbase*HH;
    float a[4];
    #pragma unroll
    for (int d=0;d<4;d++) a[d]=0.f;
    for (int t=0; t<NN; t++){
        float hr = Hb[(size_t)t*HH + c];
        float4 w0 = *(const float4*)&s_wt[t*20 + h*4];
        a[0] += w0.x*hr; a[1] += w0.y*hr; a[2] += w0.z*hr; a[3] += w0.w*hr;
    }
    float y[4];
    float bi = bias[c];
    #pragma unroll
    for (int d=0;d<4;d++){
        size_t row = (nbase + TT + half*4 + d)*HH;
        float xres = __bfloat162float(g_Ahi[row + c]) + __bfloat162float(g_Alo[row + c]);
        float agg = a[d]*s_dinv[d*4+h];
        y[d] = fmaxf(agg + bi, 0.f) + xres;
    }

    float gm = gamma[c], bt = beta[c];
    for (int d=0;d<4;d++){
        float ps = warpSum(y[d]);
        float pq = warpSum(y[d]*y[d]);
        if (lane==0){ s_red[wid]=ps; s_red2[wid]=pq; }
        __syncthreads();
        if (tid==0){
            float S=0.f,Q=0.f;
            #pragma unroll
            for (int wg=0;wg<24;wg++){ S+=s_red[wg]; Q+=s_red2[wg]; }
            float mean = S*(1.f/HH);
            float var  = Q*(1.f/HH) - mean*mean;
            s_stats[0]=mean;
            s_stats[1]=rsqrtf(fmaxf(var,0.f)+1e-5f);
        }
        __syncthreads();
        float mean=s_stats[0], rstd=s_stats[1];
        size_t row = (nbase + TT + half*4 + d)*HH;
        float o = (y[d]-mean)*rstd*gm + bt;
        __nv_bfloat16 hh = __float2bfloat16(o);
        g_Ahi[row + c] = hh;
        g_Alo[row + c] = bflo(o, hh);
        __syncthreads();
    }
}

// ---------------- launch ----------------
extern "C" void kernel_launch(void* const* d_in, const int* in_sizes, int n_in,
                              void* d_out, int out_size)
{
    const float* text = (const float*)d_in[0];
    const float* lab  = (const float*)d_in[1];
    const float* img  = (const float*)d_in[2];
    const float* Ws   = (const float*)d_in[3];
    const float* aws  = (const float*)d_in[4];
    const float* awd  = (const float*)d_in[5];
    const float* bias = (const float*)d_in[6];
    const float* gam  = (const float*)d_in[7];
    const float* bet  = (const float*)d_in[8];
    float* outp = (float*)d_out;

    cudaFuncSetAttribute(k_gemm_mma, cudaFuncAttributeMaxDynamicSharedMemorySize, GSMEM);
    cudaFuncSetAttribute(k_heavy2, cudaFuncAttributeMaxDynamicSharedMemorySize, HV_WSZ*4);
    cudaFuncSetAttribute(k_text, cudaFuncAttributeMaxDynamicSharedMemorySize, TXT_SMEM);

    k_wconv<<<(3*HH*HH + 255)/256, 256>>>(Ws);
    {
        size_t total = (size_t)BATCH*NN*H4;
        int blocks = (int)((total + 255)/256);
        k_concat<<<blocks,256>>>((const float4*)text,(const float4*)lab,(const float4*)img);
    }
    k_excl<<<BATCH,256>>>(text, lab, img);

    for (int l=0;l<3;l++){
        k_zero<<<(2*ASZ + 255)/256, 256>>>();
        k_gemm_mma<<<304, 128, GSMEM>>>(l, aws + l*HH, awd + l*HH);
        int last = (l==2);
        k_text<<<(BATCH*TT)/8, 256, TXT_SMEM>>>(bias+l*HH, gam+l*HH, bet+l*HH, outp, last);
        if (!last) k_heavy2<<<BATCH*2, 768, HV_WSZ*4>>>(bias+l*HH, gam+l*HH, bet+l*HH);
    }
}